// round 7
// baseline (speedup 1.0000x reference)
#include <cuda_runtime.h>
#include <cstdint>

#define T_STEPS 8192
#define H_DIM 256
#define E_DIM 256
#define G_DIM 1024   // 4*H
#define CL 8         // cluster size

// 32 MB scratch for xg = emb@W_ih^T + bias  (allocation-free rule: device global)
__device__ float g_xg[(size_t)T_STEPS * G_DIM];

// ---------------------------------------------------------------------------
// helpers
// ---------------------------------------------------------------------------
__device__ __forceinline__ uint32_t smem_u32(const void* p) {
    uint32_t a;
    asm("{ .reg .u64 t; cvta.to.shared.u64 t, %1; cvt.u32.u64 %0, t; }"
        : "=r"(a) : "l"(p));
    return a;
}

__device__ __forceinline__ void ffma2(unsigned long long& d,
                                      unsigned long long a,
                                      unsigned long long b) {
    asm("fma.rn.f32x2 %0, %1, %2, %0;" : "+l"(d) : "l"(a), "l"(b));
}

__device__ __forceinline__ float lo32(unsigned long long v) {
    return __uint_as_float((uint32_t)v);
}
__device__ __forceinline__ float hi32(unsigned long long v) {
    return __uint_as_float((uint32_t)(v >> 32));
}

__device__ __forceinline__ float fast_sigmoid(float x) {
    return __fdividef(1.0f, 1.0f + __expf(-x));
}
// tanh(x) = 1 - 2/(e^{2x}+1): safe at both saturations
__device__ __forceinline__ float fast_tanh(float x) {
    return 1.0f - __fdividef(2.0f, __expf(2.0f * x) + 1.0f);
}

// ---------------------------------------------------------------------------
// Kernel A: xg[t][r] = sum_k emb[tokens[t]][k] * W_ih[r][k] + (b_ih[r]+b_hh[r])
// ---------------------------------------------------------------------------
__global__ __launch_bounds__(256) void xg_gemm(const int* __restrict__ tokens,
                                               const float* __restrict__ emb,
                                               const float* __restrict__ Wih,
                                               const float* __restrict__ bih,
                                               const float* __restrict__ bhh) {
    __shared__ __align__(16) float As[32][132];
    __shared__ __align__(16) float Bs[32][132];
    __shared__ int stok[128];

    const int tid = threadIdx.x;
    const int t0 = blockIdx.y * 128;
    const int r0 = blockIdx.x * 128;

    if (tid < 128) stok[tid] = tokens[t0 + tid];
    __syncthreads();

    const int ty = tid >> 4;
    const int tx = tid & 15;

    float acc[8][8];
#pragma unroll
    for (int i = 0; i < 8; i++)
#pragma unroll
        for (int j = 0; j < 8; j++) acc[i][j] = 0.0f;

    for (int k0 = 0; k0 < E_DIM; k0 += 32) {
#pragma unroll
        for (int q = 0; q < 4; q++) {
            int v = q * 256 + tid;
            int row = v >> 3;
            int c4 = v & 7;
            float4 a = *(const float4*)(emb + (size_t)stok[row] * E_DIM + k0 + c4 * 4);
            As[c4 * 4 + 0][row] = a.x; As[c4 * 4 + 1][row] = a.y;
            As[c4 * 4 + 2][row] = a.z; As[c4 * 4 + 3][row] = a.w;
            float4 b = *(const float4*)(Wih + (size_t)(r0 + row) * E_DIM + k0 + c4 * 4);
            Bs[c4 * 4 + 0][row] = b.x; Bs[c4 * 4 + 1][row] = b.y;
            Bs[c4 * 4 + 2][row] = b.z; Bs[c4 * 4 + 3][row] = b.w;
        }
        __syncthreads();

#pragma unroll
        for (int k = 0; k < 32; k++) {
            float a[8], b[8];
            float4 a0 = *(const float4*)&As[k][ty * 8];
            float4 a1 = *(const float4*)&As[k][ty * 8 + 4];
            float4 b0 = *(const float4*)&Bs[k][tx * 8];
            float4 b1 = *(const float4*)&Bs[k][tx * 8 + 4];
            a[0]=a0.x; a[1]=a0.y; a[2]=a0.z; a[3]=a0.w;
            a[4]=a1.x; a[5]=a1.y; a[6]=a1.z; a[7]=a1.w;
            b[0]=b0.x; b[1]=b0.y; b[2]=b0.z; b[3]=b0.w;
            b[4]=b1.x; b[5]=b1.y; b[6]=b1.z; b[7]=b1.w;
#pragma unroll
            for (int i = 0; i < 8; i++)
#pragma unroll
                for (int j = 0; j < 8; j++)
                    acc[i][j] = fmaf(a[i], b[j], acc[i][j]);
        }
        __syncthreads();
    }

#pragma unroll
    for (int j = 0; j < 8; j++) {
        int r = r0 + tx * 8 + j;
        float bias = bih[r] + bhh[r];
#pragma unroll
        for (int i = 0; i < 8; i++) {
            g_xg[(size_t)(t0 + ty * 8 + i) * G_DIM + r] = acc[i][j] + bias;
        }
    }
}

// ---------------------------------------------------------------------------
// Kernel B: persistent 8-CTA cluster LSTM scan — tagged-packet handoff.
//   Every h slot is an 8B packet {f32 value, u32 step_tag}. Producers push
//   their element to all 8 CTAs with a single st.shared::cluster.v2.b32 per
//   dest (8B atomic delivery). Consumers spin on their own 32 LOCAL slots
//   (ld.volatile.shared.v4.b32) until all tags == t. No mbarriers, no bulk
//   engine, no cluster barriers, no __syncthreads in the loop — one-way
//   fabric latency only.
//
//   Double-buffer by parity. Safety: a producer reaches step t+2 only after
//   observing all of h(t+1), which implies every CTA produced h(t+1), which
//   implies every CTA finished reading buffer (t&1). So overwriting
//   buf[t&1] at step t+2 can never clobber an unread value.
//
//   Warp w owns local elems 4w..4w+3 (global E = 32*rank + 4w + eidx).
//   Lane l: eidx = l&3, K-slice s = l>>2 (8 slices x 32 floats).
// ---------------------------------------------------------------------------
__global__ __launch_bounds__(256, 1) __cluster_dims__(CL, 1, 1)
void lstm_scan(const float* __restrict__ Whh, float* __restrict__ out) {
    // hbuf[parity][element] = {value, tag} packet
    __shared__ __align__(16) unsigned long long hbuf[2][H_DIM];

    const uint32_t smem_h = smem_u32(&hbuf[0][0]);

    const int tid = threadIdx.x;
    const int w = tid >> 5;
    const int l = tid & 31;
    const int eidx = l & 3;
    const int s = l >> 2;
    uint32_t rank;
    asm("mov.u32 %0, %%cluster_ctarank;" : "=r"(rank));

    const int E = (int)rank * 32 + 4 * w + eidx;   // global h element

    // weights: 4 gate rows of element E, K slice [32s, 32s+32), packed f32x2.
    unsigned long long wt[4][16];
#pragma unroll
    for (int g = 0; g < 4; g++) {
        const unsigned long long* wr =
            (const unsigned long long*)(Whh + (size_t)(g * H_DIM + E) * H_DIM + 32 * s);
#pragma unroll
        for (int i = 0; i < 16; i++) wt[g][i] = wr[i];
    }

    // init: buf[0] = {0.0f, tag 0} (valid for t=0); buf[1] = invalid tag
    for (int i = tid; i < H_DIM; i += 256) {
        hbuf[0][i] = 0ull;                         // value 0.0, tag 0
        hbuf[1][i] = 0xFFFFFFFF00000000ull;        // tag invalid
    }
    __syncthreads();

    // producer lanes (l<4): remote slot addresses of element E in each CTA
    uint32_t dst[CL];
    if (l < 4) {
#pragma unroll
        for (int r = 0; r < CL; r++) {
            asm("mapa.shared::cluster.u32 %0, %1, %2;"
                : "=r"(dst[r]) : "r"(smem_h + (uint32_t)E * 8), "r"(r));
        }
    }

    // all CTAs' buffers initialized before any remote packet can land
    asm volatile("barrier.cluster.arrive.aligned;" ::: "memory");
    asm volatile("barrier.cluster.wait.aligned;" ::: "memory");

    float c = 0.0f;
    float xn0 = 0.f, xn1 = 0.f, xn2 = 0.f, xn3 = 0.f;
    if (l < 4) {
        xn0 = g_xg[0 * H_DIM + E];
        xn1 = g_xg[1 * H_DIM + E];
        xn2 = g_xg[2 * H_DIM + E];
        xn3 = g_xg[3 * H_DIM + E];
    }

    for (int t = 0; t < T_STEPS; t++) {
        // ---- spin-load this lane's 32 packets (K slice [32s,32s+32)) ----
        const uint32_t base = smem_h + (uint32_t)(t & 1) * (H_DIM * 8)
                            + (uint32_t)s * 256;
        const uint32_t tagw = (uint32_t)t;
        uint32_t va[32];
        for (;;) {
            uint32_t ok = 1u;
#pragma unroll
            for (int i = 0; i < 16; i++) {
                uint32_t x, y, z, u;
                asm volatile("ld.volatile.shared.v4.b32 {%0,%1,%2,%3}, [%4];"
                             : "=r"(x), "=r"(y), "=r"(z), "=r"(u)
                             : "r"(base + (uint32_t)i * 16));
                va[2 * i + 0] = x;
                va[2 * i + 1] = z;
                ok &= (uint32_t)(y == tagw) & (uint32_t)(u == tagw);
            }
            if (ok) break;
        }

        // pack values into f32x2 pairs
        unsigned long long hh[16];
#pragma unroll
        for (int j = 0; j < 16; j++) {
            asm("mov.b64 %0, {%1, %2};"
                : "=l"(hh[j]) : "r"(va[2 * j]), "r"(va[2 * j + 1]));
        }

        // ---- partial dots ----
        unsigned long long a0 = 0ull, a1 = 0ull, a2 = 0ull, a3 = 0ull;
#pragma unroll
        for (int j = 0; j < 16; j++) {
            ffma2(a0, wt[0][j], hh[j]);
            ffma2(a1, wt[1][j], hh[j]);
            ffma2(a2, wt[2][j], hh[j]);
            ffma2(a3, wt[3][j], hh[j]);
        }
        float si = lo32(a0) + hi32(a0);
        float sf = lo32(a1) + hi32(a1);
        float sg = lo32(a2) + hi32(a2);
        float so = lo32(a3) + hi32(a3);

        // reduce across 8 K-slices (lane bits 2,3,4)
#pragma unroll
        for (int off = 4; off <= 16; off <<= 1) {
            si += __shfl_xor_sync(0xFFFFFFFFu, si, off);
            sf += __shfl_xor_sync(0xFFFFFFFFu, sf, off);
            sg += __shfl_xor_sync(0xFFFFFFFFu, sg, off);
            so += __shfl_xor_sync(0xFFFFFFFFu, so, off);
        }

        // ---- activations + packet broadcast in lanes 0-3 of every warp ----
        if (l < 4) {
            float iv = fast_sigmoid(si + xn0);
            float fv = fast_sigmoid(sf + xn1);
            float gv = fast_tanh(sg + xn2);
            float ov = fast_sigmoid(so + xn3);
            c = fv * c + iv * gv;
            float hv = ov * fast_tanh(c);

            // critical path first: push tagged packets to all 8 CTAs
            if (t < T_STEPS - 1) {
                const uint32_t vbits = __float_as_uint(hv);
                const uint32_t ntag = (uint32_t)(t + 1);
                const uint32_t boff = (uint32_t)((t + 1) & 1) * (H_DIM * 8);
#pragma unroll
                for (int r = 0; r < CL; r++) {
                    asm volatile("st.shared::cluster.v2.b32 [%0], {%1,%2};"
                                 :: "r"(dst[r] + boff), "r"(vbits), "r"(ntag)
                                 : "memory");
                }
            }

            // off critical path: output + next xg prefetch
            out[(size_t)t * H_DIM + E] = hv;
            if (t == T_STEPS - 1) {
                out[(size_t)T_STEPS * H_DIM + E] = hv;
                out[(size_t)T_STEPS * H_DIM + H_DIM + E] = c;
            }
            {
                int tn = (t + 1 < T_STEPS) ? (t + 1) : t;
                const float* xr = g_xg + (size_t)tn * G_DIM + E;
                xn0 = xr[0]; xn1 = xr[256]; xn2 = xr[512]; xn3 = xr[768];
            }
        }
    }
}

// ---------------------------------------------------------------------------
extern "C" void kernel_launch(void* const* d_in, const int* in_sizes, int n_in,
                              void* d_out, int out_size) {
    const int* tokens = (const int*)d_in[0];
    const float* emb = (const float*)d_in[1];
    const float* Wih = (const float*)d_in[2];
    const float* Whh = (const float*)d_in[3];
    const float* bih = (const float*)d_in[4];
    const float* bhh = (const float*)d_in[5];
    float* out = (float*)d_out;

    dim3 gA(8, 64);
    xg_gemm<<<gA, 256>>>(tokens, emb, Wih, bih, bhh);
    lstm_scan<<<CL, 256>>>(Whh, out);
}

// round 8
// speedup vs baseline: 3.0724x; 3.0724x over previous
#include <cuda_runtime.h>
#include <cstdint>

#define T_STEPS 8192
#define H_DIM 256
#define E_DIM 256
#define G_DIM 1024   // 4*H
#define CL 8         // cluster size

// 32 MB scratch for xg = emb@W_ih^T + bias  (allocation-free rule: device global)
__device__ float g_xg[(size_t)T_STEPS * G_DIM];

// ---------------------------------------------------------------------------
// helpers
// ---------------------------------------------------------------------------
__device__ __forceinline__ uint32_t smem_u32(const void* p) {
    uint32_t a;
    asm("{ .reg .u64 t; cvta.to.shared.u64 t, %1; cvt.u32.u64 %0, t; }"
        : "=r"(a) : "l"(p));
    return a;
}

__device__ __forceinline__ void ffma2(unsigned long long& d,
                                      unsigned long long a,
                                      unsigned long long b) {
    asm("fma.rn.f32x2 %0, %1, %2, %0;" : "+l"(d) : "l"(a), "l"(b));
}
__device__ __forceinline__ void fadd2(unsigned long long& d,
                                      unsigned long long a) {
    asm("add.rn.f32x2 %0, %0, %1;" : "+l"(d) : "l"(a));
}

__device__ __forceinline__ float lo32(unsigned long long v) {
    return __uint_as_float((uint32_t)v);
}
__device__ __forceinline__ float hi32(unsigned long long v) {
    return __uint_as_float((uint32_t)(v >> 32));
}

__device__ __forceinline__ float fast_sigmoid(float x) {
    return __fdividef(1.0f, 1.0f + __expf(-x));
}
// tanh(x) = 1 - 2/(e^{2x}+1): safe at both saturations
__device__ __forceinline__ float fast_tanh(float x) {
    return 1.0f - __fdividef(2.0f, __expf(2.0f * x) + 1.0f);
}

// cluster-scope acquire wait (data arrives via remote generic stores)
__device__ __forceinline__ void mbar_wait_cl(uint32_t addr, uint32_t parity) {
    uint32_t done;
    asm volatile(
        "{\n\t.reg .pred p;\n\t"
        "mbarrier.try_wait.parity.acquire.cluster.shared::cta.b64 p, [%1], %2;\n\t"
        "selp.b32 %0, 1, 0, p;\n\t}"
        : "=r"(done) : "r"(addr), "r"(parity) : "memory");
    if (!done) {
        asm volatile(
            "{\n\t.reg .pred P1;\n"
            "WL_%=:\n\t"
            "mbarrier.try_wait.parity.acquire.cluster.shared::cta.b64 P1, [%0], %1, 0x989680;\n\t"
            "@P1 bra.uni WD_%=;\n\t"
            "bra.uni WL_%=;\n"
            "WD_%=:\n\t}"
            :: "r"(addr), "r"(parity) : "memory");
    }
}

// ---------------------------------------------------------------------------
// Kernel A: xg[t][r] = sum_k emb[tokens[t]][k] * W_ih[r][k] + (b_ih[r]+b_hh[r])
// ---------------------------------------------------------------------------
__global__ __launch_bounds__(256) void xg_gemm(const int* __restrict__ tokens,
                                               const float* __restrict__ emb,
                                               const float* __restrict__ Wih,
                                               const float* __restrict__ bih,
                                               const float* __restrict__ bhh) {
    __shared__ __align__(16) float As[32][132];
    __shared__ __align__(16) float Bs[32][132];
    __shared__ int stok[128];

    const int tid = threadIdx.x;
    const int t0 = blockIdx.y * 128;
    const int r0 = blockIdx.x * 128;

    if (tid < 128) stok[tid] = tokens[t0 + tid];
    __syncthreads();

    const int ty = tid >> 4;
    const int tx = tid & 15;

    float acc[8][8];
#pragma unroll
    for (int i = 0; i < 8; i++)
#pragma unroll
        for (int j = 0; j < 8; j++) acc[i][j] = 0.0f;

    for (int k0 = 0; k0 < E_DIM; k0 += 32) {
#pragma unroll
        for (int q = 0; q < 4; q++) {
            int v = q * 256 + tid;
            int row = v >> 3;
            int c4 = v & 7;
            float4 a = *(const float4*)(emb + (size_t)stok[row] * E_DIM + k0 + c4 * 4);
            As[c4 * 4 + 0][row] = a.x; As[c4 * 4 + 1][row] = a.y;
            As[c4 * 4 + 2][row] = a.z; As[c4 * 4 + 3][row] = a.w;
            float4 b = *(const float4*)(Wih + (size_t)(r0 + row) * E_DIM + k0 + c4 * 4);
            Bs[c4 * 4 + 0][row] = b.x; Bs[c4 * 4 + 1][row] = b.y;
            Bs[c4 * 4 + 2][row] = b.z; Bs[c4 * 4 + 3][row] = b.w;
        }
        __syncthreads();

#pragma unroll
        for (int k = 0; k < 32; k++) {
            float a[8], b[8];
            float4 a0 = *(const float4*)&As[k][ty * 8];
            float4 a1 = *(const float4*)&As[k][ty * 8 + 4];
            float4 b0 = *(const float4*)&Bs[k][tx * 8];
            float4 b1 = *(const float4*)&Bs[k][tx * 8 + 4];
            a[0]=a0.x; a[1]=a0.y; a[2]=a0.z; a[3]=a0.w;
            a[4]=a1.x; a[5]=a1.y; a[6]=a1.z; a[7]=a1.w;
            b[0]=b0.x; b[1]=b0.y; b[2]=b0.z; b[3]=b0.w;
            b[4]=b1.x; b[5]=b1.y; b[6]=b1.z; b[7]=b1.w;
#pragma unroll
            for (int i = 0; i < 8; i++)
#pragma unroll
                for (int j = 0; j < 8; j++)
                    acc[i][j] = fmaf(a[i], b[j], acc[i][j]);
        }
        __syncthreads();
    }

#pragma unroll
    for (int j = 0; j < 8; j++) {
        int r = r0 + tx * 8 + j;
        float bias = bih[r] + bhh[r];
#pragma unroll
        for (int i = 0; i < 8; i++) {
            g_xg[(size_t)(t0 + ty * 8 + i) * G_DIM + r] = acc[i][j] + bias;
        }
    }
}

// ---------------------------------------------------------------------------
// Kernel B: persistent 8-CTA cluster LSTM scan — per-source barriers.
//   Each CTA has 8 count-1 mbarriers, one per SOURCE CTA. Consumer warp w
//   (K-slice [32w,32w+32) == source CTA w's elements) waits ONLY bars[w],
//   parity (t-1)&1 (count barriers auto-rearm; one completion per step).
//   Phase 1: warp w, lane e: 4 gate partial dots for elem e over slice w.
//            STS partials into part[t&1][w][e][4] (parity double-buffered).
//   Phase 2: warp 0, lane e: sum 8 partials, activations (c in-lane),
//            push hv to all 8 CTAs' hbuf[(t+1)&1][E] via st.shared::cluster,
//            __syncwarp, lanes 0-7 single release-arrive at dest e's
//            bars[rank]. Then out + xg prefetch (off critical path).
//
//   Safety: arrive(t+1) from source s lands after s computed h(t+1), which
//   requires this CTA's push of h(t) -> this CTA passed syncthreads(t) ->
//   all its warps passed their waits and STS for step t. So barrier reuse
//   and part[]/hbuf[] double-buffers never clobber unread data.
// ---------------------------------------------------------------------------
__global__ __launch_bounds__(256, 1) __cluster_dims__(CL, 1, 1)
void lstm_scan(const float* __restrict__ Whh, float* __restrict__ out) {
    __shared__ __align__(16) float hbuf[2][H_DIM];
    __shared__ __align__(16) float part[2][8][32][4];
    __shared__ __align__(8) unsigned long long bars[CL];   // per-source

    const uint32_t smem_h = smem_u32(&hbuf[0][0]);
    const uint32_t smem_bars = smem_u32(&bars[0]);

    const int tid = threadIdx.x;
    const int w = tid >> 5;    // warp = K-slice = source CTA index
    const int e = tid & 31;    // element within CTA's 32
    uint32_t rank;
    asm("mov.u32 %0, %%cluster_ctarank;" : "=r"(rank));

    const int E = (int)rank * 32 + e;   // global h element (for warp 0 / phase 2)

    // weights: 4 gate rows of element E, K slice [32w, 32w+32), packed f32x2.
    unsigned long long wt[4][16];
#pragma unroll
    for (int g = 0; g < 4; g++) {
        const unsigned long long* wr =
            (const unsigned long long*)(Whh + (size_t)(g * H_DIM + E) * H_DIM + 32 * w);
#pragma unroll
        for (int i = 0; i < 16; i++) wt[g][i] = wr[i];
    }

    // init
    for (int i = tid; i < 2 * H_DIM; i += 256) ((float*)hbuf)[i] = 0.0f;
    if (tid < CL) {
        asm volatile("mbarrier.init.shared.b64 [%0], %1;"
                     :: "r"(smem_bars + (uint32_t)tid * 8), "r"(1) : "memory");
    }
    __syncthreads();
    asm volatile("barrier.cluster.arrive.aligned;" ::: "memory");
    asm volatile("barrier.cluster.wait.aligned;" ::: "memory");

    // warp 0: push addresses (lane e -> element E in all 8 CTAs) and
    // arrive address (lane e<8 -> dest e's bars[rank])
    uint32_t dsth[CL];
    uint32_t dstb = 0;
    if (w == 0) {
#pragma unroll
        for (int r = 0; r < CL; r++) {
            asm("mapa.shared::cluster.u32 %0, %1, %2;"
                : "=r"(dsth[r]) : "r"(smem_h + (uint32_t)E * 4), "r"(r));
        }
        if (e < CL) {
            asm("mapa.shared::cluster.u32 %0, %1, %2;"
                : "=r"(dstb) : "r"(smem_bars + rank * 8), "r"(e));
        }
    }

    float c = 0.0f;
    float xn0 = 0.f, xn1 = 0.f, xn2 = 0.f, xn3 = 0.f;
    if (w == 0) {
        xn0 = g_xg[0 * H_DIM + E];
        xn1 = g_xg[1 * H_DIM + E];
        xn2 = g_xg[2 * H_DIM + E];
        xn3 = g_xg[3 * H_DIM + E];
    }

    const uint32_t mybar = smem_bars + (uint32_t)w * 8;

    for (int t = 0; t < T_STEPS; t++) {
        // ---- wait ONLY this warp's source CTA ----
        if (t > 0) mbar_wait_cl(mybar, (uint32_t)((t - 1) & 1));

        // ---- phase 1: partial dots over slice [32w,32w+32) ----
        const ulonglong2* hp =
            (const ulonglong2*)((const char*)hbuf + (t & 1) * (H_DIM * 4) + w * 128);
        unsigned long long hh[16];
#pragma unroll
        for (int i = 0; i < 8; i++) {
            ulonglong2 q = hp[i];
            hh[2 * i + 0] = q.x;
            hh[2 * i + 1] = q.y;
        }
        unsigned long long a0 = 0ull, a1 = 0ull, a2 = 0ull, a3 = 0ull;
#pragma unroll
        for (int j = 0; j < 16; j++) {
            ffma2(a0, wt[0][j], hh[j]);
            ffma2(a1, wt[1][j], hh[j]);
            ffma2(a2, wt[2][j], hh[j]);
            ffma2(a3, wt[3][j], hh[j]);
        }
        float4 p;
        p.x = lo32(a0) + hi32(a0);   // i
        p.y = lo32(a1) + hi32(a1);   // f
        p.z = lo32(a2) + hi32(a2);   // g
        p.w = lo32(a3) + hi32(a3);   // o
        *(float4*)&part[t & 1][w][e][0] = p;
        __syncthreads();

        // ---- phase 2: warp 0 reduces + activations + push ----
        if (w == 0) {
            unsigned long long sA = 0ull, sB = 0ull;
#pragma unroll
            for (int ww = 0; ww < 8; ww++) {
                ulonglong2 v = *(const ulonglong2*)&part[t & 1][ww][e][0];
                fadd2(sA, v.x);   // (i,f)
                fadd2(sB, v.y);   // (g,o)
            }
            float iv = fast_sigmoid(lo32(sA) + xn0);
            float fv = fast_sigmoid(hi32(sA) + xn1);
            float gv = fast_tanh(lo32(sB) + xn2);
            float ov = fast_sigmoid(hi32(sB) + xn3);
            c = fv * c + iv * gv;
            float hv = ov * fast_tanh(c);

            if (t < T_STEPS - 1) {
                // critical path: push hv to all 8 CTAs, then single arrive/dest
                const uint32_t boff = (uint32_t)((t + 1) & 1) * (H_DIM * 4);
#pragma unroll
                for (int r = 0; r < CL; r++) {
                    asm volatile("st.shared::cluster.f32 [%0], %1;"
                                 :: "r"(dsth[r] + boff), "f"(hv) : "memory");
                }
                __syncwarp();
                if (e < CL) {
                    asm volatile(
                        "mbarrier.arrive.release.cluster.shared::cluster.b64 _, [%0];"
                        :: "r"(dstb) : "memory");
                }
            }

            // off critical path: output + next xg prefetch
            out[(size_t)t * H_DIM + E] = hv;
            if (t == T_STEPS - 1) {
                out[(size_t)T_STEPS * H_DIM + E] = hv;
                out[(size_t)T_STEPS * H_DIM + H_DIM + E] = c;
            }
            {
                int tn = (t + 1 < T_STEPS) ? (t + 1) : t;
                const float* xr = g_xg + (size_t)tn * G_DIM + E;
                xn0 = xr[0]; xn1 = xr[256]; xn2 = xr[512]; xn3 = xr[768];
            }
        }
    }
}

// ---------------------------------------------------------------------------
extern "C" void kernel_launch(void* const* d_in, const int* in_sizes, int n_in,
                              void* d_out, int out_size) {
    const int* tokens = (const int*)d_in[0];
    const float* emb = (const float*)d_in[1];
    const float* Wih = (const float*)d_in[2];
    const float* Whh = (const float*)d_in[3];
    const float* bih = (const float*)d_in[4];
    const float* bhh = (const float*)d_in[5];
    float* out = (float*)d_out;

    dim3 gA(8, 64);
    xg_gemm<<<gA, 256>>>(tokens, emb, Wih, bih, bhh);
    lstm_scan<<<CL, 256>>>(Whh, out);
}

// round 9
// speedup vs baseline: 5.0334x; 1.6382x over previous
#include <cuda_runtime.h>
#include <cstdint>

#define T_STEPS 8192
#define H_DIM 256
#define E_DIM 256
#define G_DIM 1024   // 4*H
#define CL 8         // cluster size

// 32 MB scratch for xg = emb@W_ih^T + bias  (allocation-free rule: device global)
__device__ float g_xg[(size_t)T_STEPS * G_DIM];

// ---------------------------------------------------------------------------
// helpers
// ---------------------------------------------------------------------------
__device__ __forceinline__ uint32_t smem_u32(const void* p) {
    uint32_t a;
    asm("{ .reg .u64 t; cvta.to.shared.u64 t, %1; cvt.u32.u64 %0, t; }"
        : "=r"(a) : "l"(p));
    return a;
}

__device__ __forceinline__ void ffma2(unsigned long long& d,
                                      unsigned long long a,
                                      unsigned long long b) {
    asm("fma.rn.f32x2 %0, %1, %2, %0;" : "+l"(d) : "l"(a), "l"(b));
}
__device__ __forceinline__ void fadd2(unsigned long long& d,
                                      unsigned long long a) {
    asm("add.rn.f32x2 %0, %0, %1;" : "+l"(d) : "l"(a));
}

__device__ __forceinline__ float lo32(unsigned long long v) {
    return __uint_as_float((uint32_t)v);
}
__device__ __forceinline__ float hi32(unsigned long long v) {
    return __uint_as_float((uint32_t)(v >> 32));
}

__device__ __forceinline__ float fast_sigmoid(float x) {
    return __fdividef(1.0f, 1.0f + __expf(-x));
}
// tanh(x) = 1 - 2/(e^{2x}+1): safe at both saturations
__device__ __forceinline__ float fast_tanh(float x) {
    return 1.0f - __fdividef(2.0f, __expf(2.0f * x) + 1.0f);
}

__device__ __forceinline__ void mbar_wait(uint32_t addr, uint32_t parity) {
    uint32_t done;
    asm volatile(
        "{\n\t.reg .pred p;\n\t"
        "mbarrier.try_wait.parity.acquire.cta.shared::cta.b64 p, [%1], %2;\n\t"
        "selp.b32 %0, 1, 0, p;\n\t}"
        : "=r"(done) : "r"(addr), "r"(parity) : "memory");
    if (!done) {
        asm volatile(
            "{\n\t.reg .pred P1;\n"
            "WL_%=:\n\t"
            "mbarrier.try_wait.parity.acquire.cta.shared::cta.b64 P1, [%0], %1, 0x989680;\n\t"
            "@P1 bra.uni WD_%=;\n\t"
            "bra.uni WL_%=;\n"
            "WD_%=:\n\t}"
            :: "r"(addr), "r"(parity) : "memory");
    }
}

// ---------------------------------------------------------------------------
// Kernel A: xg[t][r] = sum_k emb[tokens[t]][k] * W_ih[r][k] + (b_ih[r]+b_hh[r])
// ---------------------------------------------------------------------------
__global__ __launch_bounds__(256) void xg_gemm(const int* __restrict__ tokens,
                                               const float* __restrict__ emb,
                                               const float* __restrict__ Wih,
                                               const float* __restrict__ bih,
                                               const float* __restrict__ bhh) {
    __shared__ __align__(16) float As[32][132];
    __shared__ __align__(16) float Bs[32][132];
    __shared__ int stok[128];

    const int tid = threadIdx.x;
    const int t0 = blockIdx.y * 128;
    const int r0 = blockIdx.x * 128;

    if (tid < 128) stok[tid] = tokens[t0 + tid];
    __syncthreads();

    const int ty = tid >> 4;
    const int tx = tid & 15;

    float acc[8][8];
#pragma unroll
    for (int i = 0; i < 8; i++)
#pragma unroll
        for (int j = 0; j < 8; j++) acc[i][j] = 0.0f;

    for (int k0 = 0; k0 < E_DIM; k0 += 32) {
#pragma unroll
        for (int q = 0; q < 4; q++) {
            int v = q * 256 + tid;
            int row = v >> 3;
            int c4 = v & 7;
            float4 a = *(const float4*)(emb + (size_t)stok[row] * E_DIM + k0 + c4 * 4);
            As[c4 * 4 + 0][row] = a.x; As[c4 * 4 + 1][row] = a.y;
            As[c4 * 4 + 2][row] = a.z; As[c4 * 4 + 3][row] = a.w;
            float4 b = *(const float4*)(Wih + (size_t)(r0 + row) * E_DIM + k0 + c4 * 4);
            Bs[c4 * 4 + 0][row] = b.x; Bs[c4 * 4 + 1][row] = b.y;
            Bs[c4 * 4 + 2][row] = b.z; Bs[c4 * 4 + 3][row] = b.w;
        }
        __syncthreads();

#pragma unroll
        for (int k = 0; k < 32; k++) {
            float a[8], b[8];
            float4 a0 = *(const float4*)&As[k][ty * 8];
            float4 a1 = *(const float4*)&As[k][ty * 8 + 4];
            float4 b0 = *(const float4*)&Bs[k][tx * 8];
            float4 b1 = *(const float4*)&Bs[k][tx * 8 + 4];
            a[0]=a0.x; a[1]=a0.y; a[2]=a0.z; a[3]=a0.w;
            a[4]=a1.x; a[5]=a1.y; a[6]=a1.z; a[7]=a1.w;
            b[0]=b0.x; b[1]=b0.y; b[2]=b0.z; b[3]=b0.w;
            b[4]=b1.x; b[5]=b1.y; b[6]=b1.z; b[7]=b1.w;
#pragma unroll
            for (int i = 0; i < 8; i++)
#pragma unroll
                for (int j = 0; j < 8; j++)
                    acc[i][j] = fmaf(a[i], b[j], acc[i][j]);
        }
        __syncthreads();
    }

#pragma unroll
    for (int j = 0; j < 8; j++) {
        int r = r0 + tx * 8 + j;
        float bias = bih[r] + bhh[r];
#pragma unroll
        for (int i = 0; i < 8; i++) {
            g_xg[(size_t)(t0 + ty * 8 + i) * G_DIM + r] = acc[i][j] + bias;
        }
    }
}

// ---------------------------------------------------------------------------
// Kernel B: persistent 8-CTA cluster LSTM scan — st.async handoff.
//   Producers push h directly into remote SMEM with
//   st.async.shared::cluster.mbarrier::complete_tx::bytes.b64: the tx-update
//   happens at the DEST when the data lands — no release/ACK round-trip,
//   no bulk engine. Consumers sleep on per-(dest,source) mbarriers.
//
//   Barriers: bars[source][parity], count=1, expect_tx=128B per phase
//   (16 x .b64 packets from that source). Consumer warp w waits only
//   bars[w][t&1] at parity ((t-1)>>1)&1, then lane 0 re-arms it for t+2
//   (arrive.expect_tx). Pre-loop arms bars[w][1] for t=1.
//   Arm-before-tx safety: tx for t+2 are sent by a source only after it saw
//   our h(t+1), pushed by our warp0 at end of step t — after our arm at t.
//
//   Phase 1: warp w, lane e: 4 gate partial dots of elem e over slice
//            [32w,32w+32); STS into part[t&1][w][e][4].
//   Phase 2 (after one __syncthreads): warp 0 lane e: reduce 8 partials,
//            activations (c in-lane), then lanes 0-15 pack hv pairs (.b64)
//            and st.async them to all 8 CTAs + out/xg off critical path.
// ---------------------------------------------------------------------------
__global__ __launch_bounds__(256, 1) __cluster_dims__(CL, 1, 1)
void lstm_scan(const float* __restrict__ Whh, float* __restrict__ out) {
    __shared__ __align__(16) float hbuf[2][H_DIM];
    __shared__ __align__(16) float part[2][8][32][4];
    __shared__ __align__(8) unsigned long long bars[CL][2];

    const uint32_t smem_h = smem_u32(&hbuf[0][0]);
    const uint32_t smem_bars = smem_u32(&bars[0][0]);

    const int tid = threadIdx.x;
    const int w = tid >> 5;    // warp = K-slice = source CTA index
    const int e = tid & 31;    // element within CTA's 32
    uint32_t rank;
    asm("mov.u32 %0, %%cluster_ctarank;" : "=r"(rank));

    const int E = (int)rank * 32 + e;   // global h element

    // weights: 4 gate rows of element E, K slice [32w, 32w+32), packed f32x2.
    unsigned long long wt[4][16];
#pragma unroll
    for (int g = 0; g < 4; g++) {
        const unsigned long long* wr =
            (const unsigned long long*)(Whh + (size_t)(g * H_DIM + E) * H_DIM + 32 * w);
#pragma unroll
        for (int i = 0; i < 16; i++) wt[g][i] = wr[i];
    }

    // init
    for (int i = tid; i < 2 * H_DIM; i += 256) ((float*)hbuf)[i] = 0.0f;
    if (tid < 2 * CL) {
        asm volatile("mbarrier.init.shared.b64 [%0], %1;"
                     :: "r"(smem_bars + (uint32_t)tid * 8), "r"(1) : "memory");
    }
    __syncthreads();
    // pre-arm bars[w][1] for t=1 (consumer-side arm)
    if (e == 0) {
        asm volatile("mbarrier.arrive.expect_tx.shared.b64 _, [%0], %1;"
                     :: "r"(smem_bars + (uint32_t)(w * 2 + 1) * 8), "r"(128)
                     : "memory");
    }
    __syncthreads();
    asm volatile("barrier.cluster.arrive.aligned;" ::: "memory");
    asm volatile("barrier.cluster.wait.aligned;" ::: "memory");

    // producer lanes (warp 0, lanes 0-15): remote addresses per dest CTA.
    // lane i sends elements (2i, 2i+1) as one .b64 packet.
    uint32_t dsth[CL];   // remote &hbuf[0][rank*32 + 2*i]
    uint32_t dstb[CL];   // remote &bars[rank][0]
    if (w == 0 && e < 16) {
        uint32_t hoff = smem_h + (uint32_t)(rank * 32 + 2 * e) * 4;
        uint32_t boff = smem_bars + rank * 16;   // bars[rank][0]
#pragma unroll
        for (int r = 0; r < CL; r++) {
            asm("mapa.shared::cluster.u32 %0, %1, %2;"
                : "=r"(dsth[r]) : "r"(hoff), "r"(r));
            asm("mapa.shared::cluster.u32 %0, %1, %2;"
                : "=r"(dstb[r]) : "r"(boff), "r"(r));
        }
    }

    float c = 0.0f;
    float xn0 = 0.f, xn1 = 0.f, xn2 = 0.f, xn3 = 0.f;
    if (w == 0) {
        xn0 = g_xg[0 * H_DIM + E];
        xn1 = g_xg[1 * H_DIM + E];
        xn2 = g_xg[2 * H_DIM + E];
        xn3 = g_xg[3 * H_DIM + E];
    }

    const uint32_t mybar0 = smem_bars + (uint32_t)(w * 2) * 8;
    const uint32_t mybar1 = mybar0 + 8;

    for (int t = 0; t < T_STEPS; t++) {
        const uint32_t mybar = (t & 1) ? mybar1 : mybar0;
        // ---- wait ONLY this warp's source CTA, then re-arm for t+2 ----
        if (t > 0) mbar_wait(mybar, (uint32_t)(((t - 1) >> 1) & 1));
        if (e == 0) {
            asm volatile("mbarrier.arrive.expect_tx.shared.b64 _, [%0], %1;"
                         :: "r"(mybar), "r"(128) : "memory");
        }

        // ---- phase 1: partial dots over slice [32w,32w+32) ----
        const ulonglong2* hp =
            (const ulonglong2*)((const char*)hbuf + (t & 1) * (H_DIM * 4) + w * 128);
        unsigned long long hh[16];
#pragma unroll
        for (int i = 0; i < 8; i++) {
            ulonglong2 q = hp[i];
            hh[2 * i + 0] = q.x;
            hh[2 * i + 1] = q.y;
        }
        unsigned long long a0 = 0ull, a1 = 0ull, a2 = 0ull, a3 = 0ull;
#pragma unroll
        for (int j = 0; j < 16; j++) {
            ffma2(a0, wt[0][j], hh[j]);
            ffma2(a1, wt[1][j], hh[j]);
            ffma2(a2, wt[2][j], hh[j]);
            ffma2(a3, wt[3][j], hh[j]);
        }
        float4 p;
        p.x = lo32(a0) + hi32(a0);   // i
        p.y = lo32(a1) + hi32(a1);   // f
        p.z = lo32(a2) + hi32(a2);   // g
        p.w = lo32(a3) + hi32(a3);   // o
        *(float4*)&part[t & 1][w][e][0] = p;
        __syncthreads();

        // ---- phase 2: warp 0 reduces + activations + st.async push ----
        if (w == 0) {
            unsigned long long sA = 0ull, sB = 0ull;
#pragma unroll
            for (int ww = 0; ww < 8; ww++) {
                ulonglong2 v = *(const ulonglong2*)&part[t & 1][ww][e][0];
                fadd2(sA, v.x);   // (i,f)
                fadd2(sB, v.y);   // (g,o)
            }
            float iv = fast_sigmoid(lo32(sA) + xn0);
            float fv = fast_sigmoid(hi32(sA) + xn1);
            float gv = fast_tanh(lo32(sB) + xn2);
            float ov = fast_sigmoid(hi32(sB) + xn3);
            c = fv * c + iv * gv;
            float hv = ov * fast_tanh(c);

            if (t < T_STEPS - 1) {
                // pack pairs: lane i carries {hv(2i), hv(2i+1)} as b64
                float vlo = __shfl_sync(0xFFFFFFFFu, hv, 2 * (e & 15));
                float vhi = __shfl_sync(0xFFFFFFFFu, hv, 2 * (e & 15) + 1);
                if (e < 16) {
                    unsigned long long pkt;
                    asm("mov.b64 %0, {%1, %2};"
                        : "=l"(pkt) : "r"(__float_as_uint(vlo)),
                                      "r"(__float_as_uint(vhi)));
                    const uint32_t hoff = (uint32_t)((t + 1) & 1) * (H_DIM * 4);
                    const uint32_t boff = (uint32_t)((t + 1) & 1) * 8;
#pragma unroll
                    for (int r = 0; r < CL; r++) {
                        asm volatile(
                            "st.async.shared::cluster.mbarrier::complete_tx::bytes.b64 "
                            "[%0], %1, [%2];"
                            :: "r"(dsth[r] + hoff), "l"(pkt), "r"(dstb[r] + boff)
                            : "memory");
                    }
                }
            }

            // off critical path: output + next xg prefetch
            out[(size_t)t * H_DIM + E] = hv;
            if (t == T_STEPS - 1) {
                out[(size_t)T_STEPS * H_DIM + E] = hv;
                out[(size_t)T_STEPS * H_DIM + H_DIM + E] = c;
            }
            {
                int tn = (t + 1 < T_STEPS) ? (t + 1) : t;
                const float* xr = g_xg + (size_t)tn * G_DIM + E;
                xn0 = xr[0]; xn1 = xr[256]; xn2 = xr[512]; xn3 = xr[768];
            }
        }
    }
}

// ---------------------------------------------------------------------------
extern "C" void kernel_launch(void* const* d_in, const int* in_sizes, int n_in,
                              void* d_out, int out_size) {
    const int* tokens = (const int*)d_in[0];
    const float* emb = (const float*)d_in[1];
    const float* Wih = (const float*)d_in[2];
    const float* Whh = (const float*)d_in[3];
    const float* bih = (const float*)d_in[4];
    const float* bhh = (const float*)d_in[5];
    float* out = (float*)d_out;

    dim3 gA(8, 64);
    xg_gemm<<<gA, 256>>>(tokens, emb, Wih, bih, bhh);
    lstm_scan<<<CL, 256>>>(Whh, out);
}